// round 8
// baseline (speedup 1.0000x reference)
#include <cuda_runtime.h>
#include <cstdint>

#define INFV   1000000000.0f
#define ALPHA_ 0.25f
#define TPB    256
#define LPB    128          // locations per block (2 threads each)
#define MAXG   64
#define MAXBLK 4096
#define NCHAIN 4

// per-block partial sums, column-major: g_part[k*MAXBLK + blk], k in 0..4
__device__ float        g_part[5 * MAXBLK];
__device__ unsigned int g_count = 0;   // self-resetting each launch

__device__ __forceinline__ float warp_sum(float v) {
#pragma unroll
    for (int o = 16; o; o >>= 1) v += __shfl_down_sync(0xffffffffu, v, o);
    return v;
}

// 2 threads per location (halves per warp-group for smem broadcast),
// argmin split into NCHAIN independent accumulator chains for ILP.
__global__ void __launch_bounds__(TPB)
fcos_fused_kernel(const float* __restrict__ loc,
                  const float* __restrict__ cls,
                  const float* __restrict__ boxp,
                  const float* __restrict__ ctp,
                  const float* __restrict__ bbox,
                  const int*   __restrict__ glab,
                  const float* __restrict__ spt,
                  const float* __restrict__ soi,
                  float* __restrict__ out,
                  int N, int G, int C, int B, int nblk)
{
    const int b    = blockIdx.y;
    const int nl   = threadIdx.x & (LPB - 1);     // 0..127 local location
    const int half = threadIdx.x >> 7;            // warps 0-3 -> 0, warps 4-7 -> 1
    const int n    = blockIdx.x * LPB + nl;
    const bool valid = (n < N);

    __shared__ float4 s_A[MAXG];   // b0,b1,b2,b3
    __shared__ float4 s_Bv[MAXG];  // b4,b5,area,0
    __shared__ float4 s_C[MAXG];   // cx,cy,cz,0
    __shared__ int    s_lab[MAXG];
    __shared__ float  x_mina[2][LPB];
    __shared__ int    x_gid[2][LPB];
    for (int g = threadIdx.x; g < G; g += TPB) {
        const float b0 = bbox[(b * G + g) * 6 + 0];
        const float b1 = bbox[(b * G + g) * 6 + 1];
        const float b2 = bbox[(b * G + g) * 6 + 2];
        const float b3 = bbox[(b * G + g) * 6 + 3];
        const float b4 = bbox[(b * G + g) * 6 + 4];
        const float b5 = bbox[(b * G + g) * 6 + 5];
        s_A[g]  = make_float4(b0, b1, b2, b3);
        s_Bv[g] = make_float4(b4, b5, (b3 - b0) * (b4 - b1) * (b5 - b2), 0.f);
        s_C[g]  = make_float4((b0 + b3) * 0.5f, (b1 + b4) * 0.5f, (b2 + b5) * 0.5f, 0.f);
        s_lab[g] = glab[b * G + g];
    }
    __syncthreads();

    float focal = 0.f, npos = 0.f, wiou = 0.f, wsum = 0.f, bce = 0.f;

    float x = 0.f, y = 0.f, z = 0.f;
    float mina = INFV;
    int   gid  = 0;

    if (valid) {
        x = loc[n * 3 + 0];
        y = loc[n * 3 + 1];
        z = loc[n * 3 + 2];
        const float s = spt[n];
        const float2 so = *(const float2*)(soi + 2 * n);
        const float lo = so.x, hi = so.y;

        const int Gh   = (G + 1) >> 1;
        const int gbeg = half ? Gh : 0;
        const int gend = half ? G  : Gh;

        // NCHAIN independent argmin chains (strided g) to break the
        // loop-carried (v < mina) dependency.
        float cm[NCHAIN];
        int   cg[NCHAIN];
#pragma unroll
        for (int k = 0; k < NCHAIN; ++k) { cm[k] = INFV; cg[k] = 0; }

        for (int gi = gbeg; gi < gend; gi += NCHAIN) {
#pragma unroll
            for (int k = 0; k < NCHAIN; ++k) {
                const int g = gi + k;
                if (g < gend) {
                    const float4 A  = s_A[g];
                    const float4 Bv = s_Bv[g];
                    const float4 Cc = s_C[g];
                    const float l  = x - A.x, t = y - A.y, f = z - A.z;
                    const float r  = A.w - x, bo = Bv.x - y, a = Bv.y - z;
                    const float mx = fmaxf(fmaxf(fmaxf(l, t), fmaxf(f, r)), fmaxf(bo, a));
                    const float mn6 = fminf(fminf(fminf(l, t), f),
                                            fminf(fminf(r, bo), a));
                    const float inb = fminf(fminf(s - fabsf(x - Cc.x),
                                                  s - fabsf(y - Cc.y)),
                                            s - fabsf(z - Cc.z));
                    const bool ok = (fminf(mn6, inb) > 0.0f) && (mx >= lo) && (mx <= hi);
                    const float v = ok ? Bv.z : INFV;
                    if (v < cm[k]) { cm[k] = v; cg[k] = g; }
                }
            }
        }
        // merge chains: lexicographic (mina, gid) min -> first-index argmin
        mina = cm[0]; gid = cg[0];
#pragma unroll
        for (int k = 1; k < NCHAIN; ++k) {
            const bool take = (cm[k] < mina) || (cm[k] == mina && cg[k] < gid);
            if (take) { mina = cm[k]; gid = cg[k]; }
        }
    }

    // exchange (mina,gid) across halves via shared memory
    x_mina[half][nl] = mina;
    x_gid[half][nl]  = gid;
    __syncthreads();
    {
        const float om = x_mina[half ^ 1][nl];
        const int   og = x_gid[half ^ 1][nl];
        const bool take = (om < mina) || (om == mina && og < gid);
        if (take) { mina = om; gid = og; }
        // equal area across halves -> smaller gid wins: first-index ✓
    }

    if (valid) {
        const int label = (mina == INFV) ? 0 : s_lab[gid];
        const long long base = (long long)b * N + n;

        // this thread handles classes [half*4, half*4+4)
        const float4 c4 = *(const float4*)(cls + base * 8 + half * 4);
        const float cv[4] = { c4.x, c4.y, c4.z, c4.w };
#pragma unroll
        for (int c = 0; c < 4; ++c) {
            const float xl  = cv[c];
            const float ax  = fabsf(xl);
            const float e   = __expf(-ax);               // exp(-|x|)
            const float lse = __logf(1.0f + e);          // log(1+exp(-|x|))
            const float inv = __frcp_rn(1.0f + e);       // 1/(1+e)
            const float p   = (xl >= 0.0f) ? inv : e * inv;  // sigmoid(x)
            const float q   = 1.0f - p;
            const float lp  = fminf(xl, 0.0f) - lse;     // log_sigmoid(x)
            const float lnp = fminf(-xl, 0.0f) - lse;    // log_sigmoid(-x)
            const float pos_term = -ALPHA_ * q * q * lp;
            const float neg_term = -(1.0f - ALPHA_) * p * p * lnp;
            const int cls_id = half * 4 + c + 1;
            focal += (label == cls_id) ? pos_term : neg_term;
        }

        if (half == 0 && label > 0) {
            npos = 1.0f;
            // recompute box targets for the winning box
            const float4 A  = s_A[gid];
            const float4 Bv = s_Bv[gid];
            const float bt0 = x - A.x, bt1 = y - A.y, bt2 = z - A.z;
            const float bt3 = A.w - x, bt4 = Bv.x - y, bt5 = Bv.y - z;

            const float lr = fminf(bt0, bt3) / fmaxf(bt0, bt3);
            const float tb = fminf(bt1, bt4) / fmaxf(bt1, bt4);
            const float fb = fminf(bt2, bt5) / fmaxf(bt2, bt5);
            float c = lr * tb * fb;
            c = fminf(fmaxf(c, 1e-8f), 1.0f);
            const float ctr = sqrtf(c);
            wsum = ctr;

            const float* bp = boxp + base * 6;           // 8B-aligned
            const float2 q0 = *(const float2*)(bp + 0);
            const float2 q1 = *(const float2*)(bp + 2);
            const float2 q2 = *(const float2*)(bp + 4);
            const float p0 = q0.x, p1 = q0.y, p2 = q1.x;
            const float p3 = q1.y, p4 = q2.x, p5 = q2.y;
            const float pv = (p0 + p3) * (p1 + p4) * (p2 + p5);
            const float tv = (bt0 + bt3) * (bt1 + bt4) * (bt2 + bt5);
            const float m0 = fminf(p0, bt0), m1 = fminf(p1, bt1), m2 = fminf(p2, bt2);
            const float m3 = fminf(p3, bt3), m4 = fminf(p4, bt4), m5 = fminf(p5, bt5);
            const float inter = (m0 + m3) * (m1 + m4) * (m2 + m5);
            const float uni   = pv + tv - inter;
            const float ious  = (inter + 1.0f) / (uni + 1.0f);
            const float il    = -__logf(fmaxf(ious, 1e-6f));
            wiou = ctr * il;

            const float ct  = ctp[base];
            const float ec  = __expf(-fabsf(ct));
            bce = fmaxf(ct, 0.f) - ct * ctr + __logf(1.0f + ec);
        }
    }

    // block reduction of 5 accumulators -> one store per block per acc
    float vals[5] = { focal, npos, wiou, wsum, bce };
    __shared__ float red[TPB / 32][5];
    const int lane = threadIdx.x & 31;
    const int wid  = threadIdx.x >> 5;
#pragma unroll
    for (int k = 0; k < 5; ++k) {
        const float v = warp_sum(vals[k]);
        if (lane == 0) red[wid][k] = v;
    }
    __syncthreads();
    const int blk = blockIdx.y * gridDim.x + blockIdx.x;
    if (wid == 0 && lane < 5) {
        float v = 0.f;
#pragma unroll
        for (int w = 0; w < TPB / 32; ++w) v += red[w][lane];
        g_part[lane * MAXBLK + blk] = v;
    }

    // ---- last-block-done finalize (no second launch) ----
    __shared__ bool is_last;
    __threadfence();
    if (threadIdx.x == 0) {
        const unsigned int c = atomicAdd(&g_count, 1u);
        is_last = (c == (unsigned int)nblk - 1u);
    }
    __syncthreads();
    if (!is_last) return;

    double acc[5] = {0, 0, 0, 0, 0};
    for (int i = threadIdx.x; i < nblk; i += TPB) {
#pragma unroll
        for (int k = 0; k < 5; ++k) acc[k] += (double)g_part[k * MAXBLK + i];
    }
    __shared__ double dred[TPB / 32][5];
#pragma unroll
    for (int k = 0; k < 5; ++k) {
        double v = acc[k];
#pragma unroll
        for (int o = 16; o; o >>= 1) v += __shfl_down_sync(0xffffffffu, v, o);
        if (lane == 0) dred[wid][k] = v;
    }
    __syncthreads();
    if (threadIdx.x == 0) {
        double t[5];
#pragma unroll
        for (int k = 0; k < 5; ++k) {
            double v = 0.0;
#pragma unroll
            for (int w = 0; w < TPB / 32; ++w) v += dred[w][k];
            t[k] = v;
        }
        out[0] = (float)t[0] / ((float)t[1] + (float)B);
        out[1] = (float)t[2] / fmaxf((float)t[3], 1e-8f);
        out[2] = (float)t[4] / fmaxf((float)t[1], 1.0f);
        g_count = 0;   // reset for next launch / graph replay
    }
}

extern "C" void kernel_launch(void* const* d_in, const int* in_sizes, int n_in,
                              void* d_out, int out_size)
{
    const float* loc  = (const float*)d_in[0];  // [N,3]
    const float* cls  = (const float*)d_in[1];  // [B,N,C]
    const float* boxp = (const float*)d_in[2];  // [B,N,6]
    const float* ctp  = (const float*)d_in[3];  // [B,N]
    const float* bbox = (const float*)d_in[4];  // [B,G,6]
    const int*   glab = (const int*)  d_in[5];  // [B,G]
    // d_in[6] = gt_centers (unused by reference math)
    const float* spt  = (const float*)d_in[7];  // [N]
    const float* soi  = (const float*)d_in[8];  // [N,2]

    const int N = in_sizes[0] / 3;
    const int B = in_sizes[3] / N;
    const int C = in_sizes[1] / (B * N);
    const int G = in_sizes[5] / B;

    float* out = (float*)d_out;

    dim3 grid((N + LPB - 1) / LPB, B);
    const int nblk = grid.x * grid.y;
    fcos_fused_kernel<<<grid, TPB>>>(loc, cls, boxp, ctp, bbox, glab, spt, soi,
                                     out, N, G, C, B, nblk);
}

// round 9
// speedup vs baseline: 1.0908x; 1.0908x over previous
#include <cuda_runtime.h>
#include <cstdint>

#define INFV   1000000000.0f
#define ALPHA_ 0.25f
#define TPB    256
#define LPB    128          // locations per chunk (2 threads each)
#define MAXG   64
#define MAXBLK 4096
#define CPB    2            // chunks per block (persistent)

// per-block partial sums, column-major: g_part[k*MAXBLK + blk], k in 0..4
__device__ float        g_part[5 * MAXBLK];
__device__ unsigned int g_count = 0;   // self-resetting each launch

__device__ __forceinline__ float warp_sum(float v) {
#pragma unroll
    for (int o = 16; o; o >>= 1) v += __shfl_down_sync(0xffffffffu, v, o);
    return v;
}

// Persistent: each block processes CPB chunks; chunk = (image, 128-loc tile).
// 2 threads per location, halves assigned per warp-group (smem broadcast).
__global__ void __launch_bounds__(TPB)
fcos_fused_kernel(const float* __restrict__ loc,
                  const float* __restrict__ cls,
                  const float* __restrict__ boxp,
                  const float* __restrict__ ctp,
                  const float* __restrict__ bbox,
                  const int*   __restrict__ glab,
                  const float* __restrict__ spt,
                  const float* __restrict__ soi,
                  float* __restrict__ out,
                  int N, int G, int C, int B,
                  int tiles_per_img, int nchunks, int nblk)
{
    const int nl   = threadIdx.x & (LPB - 1);     // 0..127 local location
    const int half = threadIdx.x >> 7;            // warps 0-3 -> 0, warps 4-7 -> 1

    __shared__ float4 s_A[MAXG];   // b0,b1,b2,b3
    __shared__ float4 s_Bv[MAXG];  // b4,b5,area,0
    __shared__ float4 s_C[MAXG];   // cx,cy,cz,0
    __shared__ int    s_lab[MAXG];
    __shared__ float  x_mina[2][LPB];
    __shared__ int    x_gid[2][LPB];

    float focal = 0.f, npos = 0.f, wiou = 0.f, wsum = 0.f, bce = 0.f;

    for (int chunk = blockIdx.x; chunk < nchunks; chunk += gridDim.x) {
        const int b    = chunk / tiles_per_img;
        const int tile = chunk - b * tiles_per_img;
        const int n    = tile * LPB + nl;
        const bool valid = (n < N);

        __syncthreads();   // prior iteration's shared reads must complete
        for (int g = threadIdx.x; g < G; g += TPB) {
            const float b0 = bbox[(b * G + g) * 6 + 0];
            const float b1 = bbox[(b * G + g) * 6 + 1];
            const float b2 = bbox[(b * G + g) * 6 + 2];
            const float b3 = bbox[(b * G + g) * 6 + 3];
            const float b4 = bbox[(b * G + g) * 6 + 4];
            const float b5 = bbox[(b * G + g) * 6 + 5];
            s_A[g]  = make_float4(b0, b1, b2, b3);
            s_Bv[g] = make_float4(b4, b5, (b3 - b0) * (b4 - b1) * (b5 - b2), 0.f);
            s_C[g]  = make_float4((b0 + b3) * 0.5f, (b1 + b4) * 0.5f,
                                  (b2 + b5) * 0.5f, 0.f);
            s_lab[g] = glab[b * G + g];
        }
        __syncthreads();

        float x = 0.f, y = 0.f, z = 0.f;
        float mina = INFV;
        int   gid  = 0;

        if (valid) {
            x = loc[n * 3 + 0];
            y = loc[n * 3 + 1];
            z = loc[n * 3 + 2];
            const float s = spt[n];
            const float2 so = *(const float2*)(soi + 2 * n);
            const float lo = so.x, hi = so.y;

            const int Gh   = (G + 1) >> 1;
            const int gbeg = half ? Gh : 0;
            const int gend = half ? G  : Gh;

#pragma unroll 4
            for (int g = gbeg; g < gend; ++g) {
                const float4 A  = s_A[g];
                const float4 Bv = s_Bv[g];
                const float4 Cc = s_C[g];
                const float l  = x - A.x, t = y - A.y, f = z - A.z;
                const float r  = A.w - x, bo = Bv.x - y, a = Bv.y - z;
                const float mx = fmaxf(fmaxf(fmaxf(l, t), fmaxf(f, r)), fmaxf(bo, a));
                const float mn = fminf(fminf(fminf(l, t), f),
                                       fminf(fminf(r, bo), a));
                const bool cared = (mx >= lo) && (mx <= hi);

                const float inb = fminf(fminf(s - fabsf(x - Cc.x),
                                              s - fabsf(y - Cc.y)),
                                        s - fabsf(z - Cc.z));
                const bool ok = cared && (fminf(mn, inb) > 0.0f) && (Bv.z < mina);
                if (ok) { mina = Bv.z; gid = g; }   // strict < => first-min in half
            }
        }

        // exchange (mina,gid) across halves via shared memory
        x_mina[half][nl] = mina;
        x_gid[half][nl]  = gid;
        __syncthreads();
        {
            const float om = x_mina[half ^ 1][nl];
            const int   og = x_gid[half ^ 1][nl];
            const bool take = (om < mina) || (om == mina && og < gid);
            if (take) { mina = om; gid = og; }
            // equal area across halves -> smaller gid wins: first-index ✓
        }

        if (valid) {
            const int label = (mina == INFV) ? 0 : s_lab[gid];
            const long long base = (long long)b * N + n;

            // this thread handles classes [half*4, half*4+4)
            const float4 c4 = *(const float4*)(cls + base * 8 + half * 4);
            const float cv[4] = { c4.x, c4.y, c4.z, c4.w };
#pragma unroll
            for (int c = 0; c < 4; ++c) {
                const float xl  = cv[c];
                const float ax  = fabsf(xl);
                const float e   = __expf(-ax);               // exp(-|x|)
                const float lse = __logf(1.0f + e);          // log(1+exp(-|x|))
                const float inv = __frcp_rn(1.0f + e);       // 1/(1+e)
                const float p   = (xl >= 0.0f) ? inv : e * inv;  // sigmoid(x)
                const float q   = 1.0f - p;
                const float lp  = fminf(xl, 0.0f) - lse;     // log_sigmoid(x)
                const float lnp = fminf(-xl, 0.0f) - lse;    // log_sigmoid(-x)
                const float pos_term = -ALPHA_ * q * q * lp;
                const float neg_term = -(1.0f - ALPHA_) * p * p * lnp;
                const int cls_id = half * 4 + c + 1;
                focal += (label == cls_id) ? pos_term : neg_term;
            }

            if (half == 0 && label > 0) {
                npos += 1.0f;
                const float4 A  = s_A[gid];
                const float4 Bv = s_Bv[gid];
                const float bt0 = x - A.x, bt1 = y - A.y, bt2 = z - A.z;
                const float bt3 = A.w - x, bt4 = Bv.x - y, bt5 = Bv.y - z;

                const float lr = fminf(bt0, bt3) / fmaxf(bt0, bt3);
                const float tb = fminf(bt1, bt4) / fmaxf(bt1, bt4);
                const float fb = fminf(bt2, bt5) / fmaxf(bt2, bt5);
                float c = lr * tb * fb;
                c = fminf(fmaxf(c, 1e-8f), 1.0f);
                const float ctr = sqrtf(c);
                wsum += ctr;

                const float* bp = boxp + base * 6;           // 8B-aligned
                const float2 q0 = *(const float2*)(bp + 0);
                const float2 q1 = *(const float2*)(bp + 2);
                const float2 q2 = *(const float2*)(bp + 4);
                const float p0 = q0.x, p1 = q0.y, p2 = q1.x;
                const float p3 = q1.y, p4 = q2.x, p5 = q2.y;
                const float pv = (p0 + p3) * (p1 + p4) * (p2 + p5);
                const float tv = (bt0 + bt3) * (bt1 + bt4) * (bt2 + bt5);
                const float m0 = fminf(p0, bt0), m1 = fminf(p1, bt1), m2 = fminf(p2, bt2);
                const float m3 = fminf(p3, bt3), m4 = fminf(p4, bt4), m5 = fminf(p5, bt5);
                const float inter = (m0 + m3) * (m1 + m4) * (m2 + m5);
                const float uni   = pv + tv - inter;
                const float ious  = (inter + 1.0f) / (uni + 1.0f);
                const float il    = -__logf(fmaxf(ious, 1e-6f));
                wiou += ctr * il;

                const float ct  = ctp[base];
                const float ec  = __expf(-fabsf(ct));
                bce += fmaxf(ct, 0.f) - ct * ctr + __logf(1.0f + ec);
            }
        }
    }

    // block reduction of 5 accumulators -> one store per block per acc
    float vals[5] = { focal, npos, wiou, wsum, bce };
    __shared__ float red[TPB / 32][5];
    const int lane = threadIdx.x & 31;
    const int wid  = threadIdx.x >> 5;
#pragma unroll
    for (int k = 0; k < 5; ++k) {
        const float v = warp_sum(vals[k]);
        if (lane == 0) red[wid][k] = v;
    }
    __syncthreads();
    if (wid == 0 && lane < 5) {
        float v = 0.f;
#pragma unroll
        for (int w = 0; w < TPB / 32; ++w) v += red[w][lane];
        g_part[lane * MAXBLK + blockIdx.x] = v;
    }

    // ---- last-block-done finalize (no second launch) ----
    __shared__ bool is_last;
    __threadfence();
    if (threadIdx.x == 0) {
        const unsigned int c = atomicAdd(&g_count, 1u);
        is_last = (c == (unsigned int)nblk - 1u);
    }
    __syncthreads();
    if (!is_last) return;

    double acc[5] = {0, 0, 0, 0, 0};
    for (int i = threadIdx.x; i < nblk; i += TPB) {
#pragma unroll
        for (int k = 0; k < 5; ++k) acc[k] += (double)g_part[k * MAXBLK + i];
    }
    __shared__ double dred[TPB / 32][5];
#pragma unroll
    for (int k = 0; k < 5; ++k) {
        double v = acc[k];
#pragma unroll
        for (int o = 16; o; o >>= 1) v += __shfl_down_sync(0xffffffffu, v, o);
        if (lane == 0) dred[wid][k] = v;
    }
    __syncthreads();
    if (threadIdx.x == 0) {
        double t[5];
#pragma unroll
        for (int k = 0; k < 5; ++k) {
            double v = 0.0;
#pragma unroll
            for (int w = 0; w < TPB / 32; ++w) v += dred[w][k];
            t[k] = v;
        }
        out[0] = (float)t[0] / ((float)t[1] + (float)B);
        out[1] = (float)t[2] / fmaxf((float)t[3], 1e-8f);
        out[2] = (float)t[4] / fmaxf((float)t[1], 1.0f);
        g_count = 0;   // reset for next launch / graph replay
    }
}

extern "C" void kernel_launch(void* const* d_in, const int* in_sizes, int n_in,
                              void* d_out, int out_size)
{
    const float* loc  = (const float*)d_in[0];  // [N,3]
    const float* cls  = (const float*)d_in[1];  // [B,N,C]
    const float* boxp = (const float*)d_in[2];  // [B,N,6]
    const float* ctp  = (const float*)d_in[3];  // [B,N]
    const float* bbox = (const float*)d_in[4];  // [B,G,6]
    const int*   glab = (const int*)  d_in[5];  // [B,G]
    // d_in[6] = gt_centers (unused by reference math)
    const float* spt  = (const float*)d_in[7];  // [N]
    const float* soi  = (const float*)d_in[8];  // [N,2]

    const int N = in_sizes[0] / 3;
    const int B = in_sizes[3] / N;
    const int C = in_sizes[1] / (B * N);
    const int G = in_sizes[5] / B;

    float* out = (float*)d_out;

    const int tiles_per_img = (N + LPB - 1) / LPB;
    const int nchunks = tiles_per_img * B;
    int nblk = (nchunks + CPB - 1) / CPB;        // one wave, each block does CPB chunks
    if (nblk > MAXBLK) nblk = MAXBLK;

    fcos_fused_kernel<<<nblk, TPB>>>(loc, cls, boxp, ctp, bbox, glab, spt, soi,
                                     out, N, G, C, B, tiles_per_img, nchunks, nblk);
}

// round 10
// speedup vs baseline: 1.4817x; 1.3584x over previous
#include <cuda_runtime.h>
#include <cstdint>

#define INFV   1000000000.0f
#define ALPHA_ 0.25f
#define TPB    256
#define MAXG   64
#define MAXBLK 4096

// per-block partial sums, column-major: g_part[k*MAXBLK + blk], k in 0..4
__device__ float        g_part[5 * MAXBLK];
__device__ unsigned int g_count = 0;   // self-resetting each launch

__device__ __forceinline__ float warp_min(float v) {
#pragma unroll
    for (int o = 16; o; o >>= 1) v = fminf(v, __shfl_xor_sync(0xffffffffu, v, o));
    return v;
}
__device__ __forceinline__ float warp_max(float v) {
#pragma unroll
    for (int o = 16; o; o >>= 1) v = fmaxf(v, __shfl_xor_sync(0xffffffffu, v, o));
    return v;
}
__device__ __forceinline__ float warp_sum(float v) {
#pragma unroll
    for (int o = 16; o; o >>= 1) v += __shfl_down_sync(0xffffffffu, v, o);
    return v;
}

// 1 thread per location; per-tile box prefilter + ordered compaction.
__global__ void __launch_bounds__(TPB)
fcos_fused_kernel(const float* __restrict__ loc,
                  const float* __restrict__ cls,
                  const float* __restrict__ boxp,
                  const float* __restrict__ ctp,
                  const float* __restrict__ bbox,
                  const int*   __restrict__ glab,
                  const float* __restrict__ spt,
                  const float* __restrict__ soi,
                  float* __restrict__ out,
                  int N, int G, int C, int B, int nblk)
{
    const int b = blockIdx.y;
    const int n = blockIdx.x * TPB + threadIdx.x;
    const bool valid = (n < N);

    __shared__ float4 s_A[MAXG];    // b0,b1,b2,b3
    __shared__ float4 s_Bv[MAXG];   // b4,b5,area,0
    __shared__ float4 s_C[MAXG];    // cx,cy,cz,0
    __shared__ int    s_lab[MAXG];
    __shared__ int    s_idx[MAXG];  // compacted surviving box ids (ascending)
    __shared__ int    s_M;          // number of survivors
    __shared__ float  s_bounds[7];  // xmin,xmax,ymin,ymax,zmin,zmax,smax
    __shared__ float  wred[TPB / 32][7];
    __shared__ unsigned int s_w0mask;

    // load boxes + precompute
    for (int g = threadIdx.x; g < G; g += TPB) {
        const float b0 = bbox[(b * G + g) * 6 + 0];
        const float b1 = bbox[(b * G + g) * 6 + 1];
        const float b2 = bbox[(b * G + g) * 6 + 2];
        const float b3 = bbox[(b * G + g) * 6 + 3];
        const float b4 = bbox[(b * G + g) * 6 + 4];
        const float b5 = bbox[(b * G + g) * 6 + 5];
        s_A[g]  = make_float4(b0, b1, b2, b3);
        s_Bv[g] = make_float4(b4, b5, (b3 - b0) * (b4 - b1) * (b5 - b2), 0.f);
        s_C[g]  = make_float4((b0 + b3) * 0.5f, (b1 + b4) * 0.5f, (b2 + b5) * 0.5f, 0.f);
        s_lab[g] = glab[b * G + g];
    }

    // per-thread location data
    float x = 0.f, y = 0.f, z = 0.f, s = 0.f, lo = 0.f, hi = 0.f;
    if (valid) {
        x = loc[n * 3 + 0];
        y = loc[n * 3 + 1];
        z = loc[n * 3 + 2];
        s = spt[n];
        const float2 so = *(const float2*)(soi + 2 * n);
        lo = so.x; hi = so.y;
    }

    // tile bounds reduction (invalid threads neutral)
    {
        float xmn = valid ? x : INFV,  xmx = valid ? x : -INFV;
        float ymn = valid ? y : INFV,  ymx = valid ? y : -INFV;
        float zmn = valid ? z : INFV,  zmx = valid ? z : -INFV;
        float smx = valid ? s : 0.f;
        xmn = warp_min(xmn); xmx = warp_max(xmx);
        ymn = warp_min(ymn); ymx = warp_max(ymx);
        zmn = warp_min(zmn); zmx = warp_max(zmx);
        smx = warp_max(smx);
        const int lane = threadIdx.x & 31;
        const int wid  = threadIdx.x >> 5;
        if (lane == 0) {
            wred[wid][0] = xmn; wred[wid][1] = xmx;
            wred[wid][2] = ymn; wred[wid][3] = ymx;
            wred[wid][4] = zmn; wred[wid][5] = zmx;
            wred[wid][6] = smx;
        }
        __syncthreads();
        if (threadIdx.x == 0) {
            float v0 = INFV, v1 = -INFV, v2 = INFV, v3 = -INFV, v4 = INFV, v5 = -INFV, v6 = 0.f;
#pragma unroll
            for (int w = 0; w < TPB / 32; ++w) {
                v0 = fminf(v0, wred[w][0]); v1 = fmaxf(v1, wred[w][1]);
                v2 = fminf(v2, wred[w][2]); v3 = fmaxf(v3, wred[w][3]);
                v4 = fminf(v4, wred[w][4]); v5 = fmaxf(v5, wred[w][5]);
                v6 = fmaxf(v6, wred[w][6]);
            }
            s_bounds[0] = v0; s_bounds[1] = v1; s_bounds[2] = v2; s_bounds[3] = v3;
            s_bounds[4] = v4; s_bounds[5] = v5; s_bounds[6] = v6;
            s_M = 0;
        }
        __syncthreads();
    }

    // conservative per-tile box filter + ordered compaction (threads 0..G-1)
    {
        bool pred = false;
        if (threadIdx.x < G) {
            const int g = threadIdx.x;
            const float4 A  = s_A[g];
            const float4 Bv = s_Bv[g];
            const float4 Cc = s_C[g];
            const float smx = s_bounds[6];
            // sampling region per axis (using smax: superset of any loc's region)
            const float lox = fmaxf(Cc.x - smx, A.x), hix = fminf(Cc.x + smx, A.w);
            const float loy = fmaxf(Cc.y - smx, A.y), hiy = fminf(Cc.y + smx, Bv.x);
            const float loz = fmaxf(Cc.z - smx, A.z), hiz = fminf(Cc.z + smx, Bv.y);
            pred = (s_bounds[1] > lox) && (s_bounds[0] < hix) &&
                   (s_bounds[3] > loy) && (s_bounds[2] < hiy) &&
                   (s_bounds[5] > loz) && (s_bounds[4] < hiz);
        }
        const unsigned int mask = __ballot_sync(0xffffffffu, pred);
        const int lane = threadIdx.x & 31;
        const int wid  = threadIdx.x >> 5;
        if (wid == 0 && lane == 0) s_w0mask = mask;
        __syncthreads();
        if (threadIdx.x < G && pred) {
            int off = __popc(mask & ((1u << lane) - 1u));
            if (wid == 1) off += __popc(s_w0mask);
            s_idx[off] = threadIdx.x;
        }
        if (threadIdx.x < G && (threadIdx.x >> 5) <= ((G - 1) >> 5)) {
            // thread G-1's warp leader publishes total count
        }
        if (threadIdx.x == 0) {
            // recompute total from masks after sync below
        }
        // total survivors
        if (lane == 0 && wid <= ((G - 1) >> 5)) atomicAdd(&s_M, __popc(mask));
        __syncthreads();
    }

    float focal = 0.f, npos = 0.f, wiou = 0.f, wsum = 0.f, bce = 0.f;

    if (valid) {
        float mina = INFV;
        int   gid  = 0;
        const int M = s_M;

        for (int j = 0; j < M; ++j) {
            const int g = s_idx[j];
            const float4 A  = s_A[g];
            const float4 Bv = s_Bv[g];
            const float4 Cc = s_C[g];
            const float l  = x - A.x, t = y - A.y, f = z - A.z;
            const float r  = A.w - x, bo = Bv.x - y, a = Bv.y - z;
            const float mx = fmaxf(fmaxf(fmaxf(l, t), fmaxf(f, r)), fmaxf(bo, a));
            const float mn = fminf(fminf(fminf(l, t), f), fminf(fminf(r, bo), a));
            const bool cared = (mx >= lo) && (mx <= hi);
            const float inb = fminf(fminf(s - fabsf(x - Cc.x), s - fabsf(y - Cc.y)),
                                    s - fabsf(z - Cc.z));
            const bool ok = cared && (fminf(mn, inb) > 0.0f) && (Bv.z < mina);
            if (ok) { mina = Bv.z; gid = g; }   // ascending g => first-min ✓
        }
        const int label = (mina == INFV) ? 0 : s_lab[gid];

        const long long base = (long long)b * N + n;
        const float4 c0 = *(const float4*)(cls + base * 8);
        const float4 c1 = *(const float4*)(cls + base * 8 + 4);
        const float cv[8] = { c0.x, c0.y, c0.z, c0.w, c1.x, c1.y, c1.z, c1.w };
#pragma unroll
        for (int c = 0; c < 8; ++c) {
            const float xl  = cv[c];
            const float ax  = fabsf(xl);
            const float e   = __expf(-ax);               // exp(-|x|)
            const float lse = __logf(1.0f + e);          // log(1+exp(-|x|))
            const float inv = __frcp_rn(1.0f + e);       // 1/(1+e)
            const float p   = (xl >= 0.0f) ? inv : e * inv;  // sigmoid(x)
            const float q   = 1.0f - p;
            const float lp  = fminf(xl, 0.0f) - lse;     // log_sigmoid(x)
            const float lnp = fminf(-xl, 0.0f) - lse;    // log_sigmoid(-x)
            const float pos_term = -ALPHA_ * q * q * lp;
            const float neg_term = -(1.0f - ALPHA_) * p * p * lnp;
            focal += (label == c + 1) ? pos_term : neg_term;
        }

        if (label > 0) {
            npos = 1.0f;
            const float4 A  = s_A[gid];
            const float4 Bv = s_Bv[gid];
            const float bt0 = x - A.x, bt1 = y - A.y, bt2 = z - A.z;
            const float bt3 = A.w - x, bt4 = Bv.x - y, bt5 = Bv.y - z;

            const float lr = fminf(bt0, bt3) / fmaxf(bt0, bt3);
            const float tb = fminf(bt1, bt4) / fmaxf(bt1, bt4);
            const float fb = fminf(bt2, bt5) / fmaxf(bt2, bt5);
            float c = lr * tb * fb;
            c = fminf(fmaxf(c, 1e-8f), 1.0f);
            const float ctr = sqrtf(c);
            wsum = ctr;

            const float* bp = boxp + base * 6;
            const float2 q0 = *(const float2*)(bp + 0);
            const float2 q1 = *(const float2*)(bp + 2);
            const float2 q2 = *(const float2*)(bp + 4);
            const float p0 = q0.x, p1 = q0.y, p2 = q1.x;
            const float p3 = q1.y, p4 = q2.x, p5 = q2.y;
            const float pv = (p0 + p3) * (p1 + p4) * (p2 + p5);
            const float tv = (bt0 + bt3) * (bt1 + bt4) * (bt2 + bt5);
            const float m0 = fminf(p0, bt0), m1 = fminf(p1, bt1), m2 = fminf(p2, bt2);
            const float m3 = fminf(p3, bt3), m4 = fminf(p4, bt4), m5 = fminf(p5, bt5);
            const float inter = (m0 + m3) * (m1 + m4) * (m2 + m5);
            const float uni   = pv + tv - inter;
            const float ious  = (inter + 1.0f) / (uni + 1.0f);
            const float il    = -__logf(fmaxf(ious, 1e-6f));
            wiou = ctr * il;

            const float ct  = ctp[base];
            const float ec  = __expf(-fabsf(ct));
            bce = fmaxf(ct, 0.f) - ct * ctr + __logf(1.0f + ec);
        }
    }

    // block reduction of 5 accumulators -> one store per block per acc
    float vals[5] = { focal, npos, wiou, wsum, bce };
    __shared__ float red[TPB / 32][5];
    const int lane = threadIdx.x & 31;
    const int wid  = threadIdx.x >> 5;
#pragma unroll
    for (int k = 0; k < 5; ++k) {
        const float v = warp_sum(vals[k]);
        if (lane == 0) red[wid][k] = v;
    }
    __syncthreads();
    const int blk = blockIdx.y * gridDim.x + blockIdx.x;
    if (wid == 0 && lane < 5) {
        float v = 0.f;
#pragma unroll
        for (int w = 0; w < TPB / 32; ++w) v += red[w][lane];
        g_part[lane * MAXBLK + blk] = v;
    }

    // ---- last-block-done finalize ----
    __shared__ bool is_last;
    __threadfence();
    if (threadIdx.x == 0) {
        const unsigned int c = atomicAdd(&g_count, 1u);
        is_last = (c == (unsigned int)nblk - 1u);
    }
    __syncthreads();
    if (!is_last) return;

    double acc[5] = {0, 0, 0, 0, 0};
    for (int i = threadIdx.x; i < nblk; i += TPB) {
#pragma unroll
        for (int k = 0; k < 5; ++k) acc[k] += (double)g_part[k * MAXBLK + i];
    }
    __shared__ double dred[TPB / 32][5];
#pragma unroll
    for (int k = 0; k < 5; ++k) {
        double v = acc[k];
#pragma unroll
        for (int o = 16; o; o >>= 1) v += __shfl_down_sync(0xffffffffu, v, o);
        if (lane == 0) dred[wid][k] = v;
    }
    __syncthreads();
    if (threadIdx.x == 0) {
        double t[5];
#pragma unroll
        for (int k = 0; k < 5; ++k) {
            double v = 0.0;
#pragma unroll
            for (int w = 0; w < TPB / 32; ++w) v += dred[w][k];
            t[k] = v;
        }
        out[0] = (float)t[0] / ((float)t[1] + (float)B);
        out[1] = (float)t[2] / fmaxf((float)t[3], 1e-8f);
        out[2] = (float)t[4] / fmaxf((float)t[1], 1.0f);
        g_count = 0;   // reset for next launch / graph replay
    }
}

extern "C" void kernel_launch(void* const* d_in, const int* in_sizes, int n_in,
                              void* d_out, int out_size)
{
    const float* loc  = (const float*)d_in[0];  // [N,3]
    const float* cls  = (const float*)d_in[1];  // [B,N,C]
    const float* boxp = (const float*)d_in[2];  // [B,N,6]
    const float* ctp  = (const float*)d_in[3];  // [B,N]
    const float* bbox = (const float*)d_in[4];  // [B,G,6]
    const int*   glab = (const int*)  d_in[5];  // [B,G]
    // d_in[6] = gt_centers (unused by reference math)
    const float* spt  = (const float*)d_in[7];  // [N]
    const float* soi  = (const float*)d_in[8];  // [N,2]

    const int N = in_sizes[0] / 3;
    const int B = in_sizes[3] / N;
    const int C = in_sizes[1] / (B * N);
    const int G = in_sizes[5] / B;

    float* out = (float*)d_out;

    dim3 grid((N + TPB - 1) / TPB, B);
    const int nblk = grid.x * grid.y;
    fcos_fused_kernel<<<grid, TPB>>>(loc, cls, boxp, ctp, bbox, glab, spt, soi,
                                     out, N, G, C, B, nblk);
}

// round 11
// speedup vs baseline: 1.4846x; 1.0019x over previous
#include <cuda_runtime.h>
#include <cstdint>

#define INFV   1000000000.0f
#define ALPHA_ 0.25f
#define TPB    256
#define MAXG   64
#define MAXBLK 4096

// per-block partial sums, column-major: g_part[k*MAXBLK + blk], k in 0..4
__device__ float        g_part[5 * MAXBLK];
__device__ unsigned int g_count = 0;   // self-resetting each launch

__device__ __forceinline__ float warp_min(float v) {
#pragma unroll
    for (int o = 16; o; o >>= 1) v = fminf(v, __shfl_xor_sync(0xffffffffu, v, o));
    return v;
}
__device__ __forceinline__ float warp_max(float v) {
#pragma unroll
    for (int o = 16; o; o >>= 1) v = fmaxf(v, __shfl_xor_sync(0xffffffffu, v, o));
    return v;
}
__device__ __forceinline__ float warp_sum(float v) {
#pragma unroll
    for (int o = 16; o; o >>= 1) v += __shfl_down_sync(0xffffffffu, v, o);
    return v;
}

// 1 thread/location; all global loads issued up-front (MLP), then
// per-tile box prefilter + ordered compaction, then exact argmin on survivors.
__global__ void __launch_bounds__(TPB)
fcos_fused_kernel(const float* __restrict__ loc,
                  const float* __restrict__ cls,
                  const float* __restrict__ boxp,
                  const float* __restrict__ ctp,
                  const float* __restrict__ bbox,
                  const int*   __restrict__ glab,
                  const float* __restrict__ spt,
                  const float* __restrict__ soi,
                  float* __restrict__ out,
                  int N, int G, int C, int B, int nblk)
{
    const int b = blockIdx.y;
    const int n = blockIdx.x * TPB + threadIdx.x;
    const bool valid = (n < N);
    const int nc = valid ? n : (N - 1);   // clamp: safe dummy loads for tail threads

    // ---- issue ALL per-thread global loads first (8+ independent, MLP) ----
    const long long base = (long long)b * N + nc;
    const float  lx = loc[nc * 3 + 0];
    const float  ly = loc[nc * 3 + 1];
    const float  lz = loc[nc * 3 + 2];
    const float  s  = spt[nc];
    const float2 so = *(const float2*)(soi + 2 * nc);
    const float4 c0 = *(const float4*)(cls + base * 8);
    const float4 c1 = *(const float4*)(cls + base * 8 + 4);
    const float2 bq0 = *(const float2*)(boxp + base * 6 + 0);
    const float2 bq1 = *(const float2*)(boxp + base * 6 + 2);
    const float2 bq2 = *(const float2*)(boxp + base * 6 + 4);
    const float  ct  = ctp[base];

    __shared__ float  s_raw[MAXG * 6];  // coalesced staging
    __shared__ float4 s_A[MAXG];        // b0,b1,b2,b3
    __shared__ float4 s_Bv[MAXG];       // b4,b5,area,0
    __shared__ float4 s_C[MAXG];        // cx,cy,cz,0
    __shared__ int    s_lab[MAXG];
    __shared__ int    s_idx[MAXG];      // compacted surviving box ids (ascending)
    __shared__ int    s_M;
    __shared__ float  s_bounds[7];      // xmin,xmax,ymin,ymax,zmin,zmax,smax
    __shared__ float  wred[TPB / 32][7];
    __shared__ unsigned int s_w0mask;

    // coalesced bbox staging + labels
    for (int i = threadIdx.x; i < G * 6; i += TPB) s_raw[i] = bbox[b * G * 6 + i];
    for (int g = threadIdx.x; g < G; g += TPB)     s_lab[g] = glab[b * G + g];
    __syncthreads();
    for (int g = threadIdx.x; g < G; g += TPB) {
        const float b0 = s_raw[g*6+0], b1 = s_raw[g*6+1], b2 = s_raw[g*6+2];
        const float b3 = s_raw[g*6+3], b4 = s_raw[g*6+4], b5 = s_raw[g*6+5];
        s_A[g]  = make_float4(b0, b1, b2, b3);
        s_Bv[g] = make_float4(b4, b5, (b3 - b0) * (b4 - b1) * (b5 - b2), 0.f);
        s_C[g]  = make_float4((b0 + b3) * 0.5f, (b1 + b4) * 0.5f, (b2 + b5) * 0.5f, 0.f);
    }

    const float x = lx, y = ly, z = lz;
    const float lo = so.x, hi = so.y;

    // tile bounds reduction (invalid threads neutral)
    {
        float xmn = valid ? x : INFV,  xmx = valid ? x : -INFV;
        float ymn = valid ? y : INFV,  ymx = valid ? y : -INFV;
        float zmn = valid ? z : INFV,  zmx = valid ? z : -INFV;
        float smx = valid ? s : 0.f;
        xmn = warp_min(xmn); xmx = warp_max(xmx);
        ymn = warp_min(ymn); ymx = warp_max(ymx);
        zmn = warp_min(zmn); zmx = warp_max(zmx);
        smx = warp_max(smx);
        const int lane = threadIdx.x & 31;
        const int wid  = threadIdx.x >> 5;
        if (lane == 0) {
            wred[wid][0] = xmn; wred[wid][1] = xmx;
            wred[wid][2] = ymn; wred[wid][3] = ymx;
            wred[wid][4] = zmn; wred[wid][5] = zmx;
            wred[wid][6] = smx;
        }
        __syncthreads();
        if (threadIdx.x == 0) {
            float v0 = INFV, v1 = -INFV, v2 = INFV, v3 = -INFV, v4 = INFV, v5 = -INFV, v6 = 0.f;
#pragma unroll
            for (int w = 0; w < TPB / 32; ++w) {
                v0 = fminf(v0, wred[w][0]); v1 = fmaxf(v1, wred[w][1]);
                v2 = fminf(v2, wred[w][2]); v3 = fmaxf(v3, wred[w][3]);
                v4 = fminf(v4, wred[w][4]); v5 = fmaxf(v5, wred[w][5]);
                v6 = fmaxf(v6, wred[w][6]);
            }
            s_bounds[0] = v0; s_bounds[1] = v1; s_bounds[2] = v2; s_bounds[3] = v3;
            s_bounds[4] = v4; s_bounds[5] = v5; s_bounds[6] = v6;
            s_M = 0;
        }
        __syncthreads();
    }

    // conservative per-tile box filter + ordered compaction (threads 0..G-1)
    {
        bool pred = false;
        if (threadIdx.x < G) {
            const int g = threadIdx.x;
            const float4 A  = s_A[g];
            const float4 Bv = s_Bv[g];
            const float4 Cc = s_C[g];
            const float smx = s_bounds[6];
            const float lox = fmaxf(Cc.x - smx, A.x), hix = fminf(Cc.x + smx, A.w);
            const float loy = fmaxf(Cc.y - smx, A.y), hiy = fminf(Cc.y + smx, Bv.x);
            const float loz = fmaxf(Cc.z - smx, A.z), hiz = fminf(Cc.z + smx, Bv.y);
            pred = (s_bounds[1] > lox) && (s_bounds[0] < hix) &&
                   (s_bounds[3] > loy) && (s_bounds[2] < hiy) &&
                   (s_bounds[5] > loz) && (s_bounds[4] < hiz);
        }
        const unsigned int mask = __ballot_sync(0xffffffffu, pred);
        const int lane = threadIdx.x & 31;
        const int wid  = threadIdx.x >> 5;
        if (wid == 0 && lane == 0) s_w0mask = mask;
        __syncthreads();
        if (threadIdx.x < G && pred) {
            int off = __popc(mask & ((1u << lane) - 1u));
            if (wid == 1) off += __popc(s_w0mask);
            s_idx[off] = threadIdx.x;
        }
        if (lane == 0 && wid <= ((G - 1) >> 5)) atomicAdd(&s_M, __popc(mask));
        __syncthreads();
    }

    float focal = 0.f, npos = 0.f, wiou = 0.f, wsum = 0.f, bce = 0.f;

    if (valid) {
        float mina = INFV;
        int   gid  = 0;
        const int M = s_M;

        for (int j = 0; j < M; ++j) {
            const int g = s_idx[j];
            const float4 A  = s_A[g];
            const float4 Bv = s_Bv[g];
            const float4 Cc = s_C[g];
            const float l  = x - A.x, t = y - A.y, f = z - A.z;
            const float r  = A.w - x, bo = Bv.x - y, a = Bv.y - z;
            const float mx = fmaxf(fmaxf(fmaxf(l, t), fmaxf(f, r)), fmaxf(bo, a));
            const float mn = fminf(fminf(fminf(l, t), f), fminf(fminf(r, bo), a));
            const bool cared = (mx >= lo) && (mx <= hi);
            const float inb = fminf(fminf(s - fabsf(x - Cc.x), s - fabsf(y - Cc.y)),
                                    s - fabsf(z - Cc.z));
            const bool ok = cared && (fminf(mn, inb) > 0.0f) && (Bv.z < mina);
            if (ok) { mina = Bv.z; gid = g; }   // ascending g => first-min ✓
        }
        const int label = (mina == INFV) ? 0 : s_lab[gid];

        const float cv[8] = { c0.x, c0.y, c0.z, c0.w, c1.x, c1.y, c1.z, c1.w };
#pragma unroll
        for (int c = 0; c < 8; ++c) {
            const float xl  = cv[c];
            const float ax  = fabsf(xl);
            const float e   = __expf(-ax);               // exp(-|x|)
            const float lse = __logf(1.0f + e);          // log(1+exp(-|x|))
            const float inv = __frcp_rn(1.0f + e);       // 1/(1+e)
            const float p   = (xl >= 0.0f) ? inv : e * inv;  // sigmoid(x)
            const float q   = 1.0f - p;
            const float lp  = fminf(xl, 0.0f) - lse;     // log_sigmoid(x)
            const float lnp = fminf(-xl, 0.0f) - lse;    // log_sigmoid(-x)
            const float pos_term = -ALPHA_ * q * q * lp;
            const float neg_term = -(1.0f - ALPHA_) * p * p * lnp;
            focal += (label == c + 1) ? pos_term : neg_term;
        }

        if (label > 0) {
            npos = 1.0f;
            const float4 A  = s_A[gid];
            const float4 Bv = s_Bv[gid];
            const float bt0 = x - A.x, bt1 = y - A.y, bt2 = z - A.z;
            const float bt3 = A.w - x, bt4 = Bv.x - y, bt5 = Bv.y - z;

            const float lr = fminf(bt0, bt3) / fmaxf(bt0, bt3);
            const float tb = fminf(bt1, bt4) / fmaxf(bt1, bt4);
            const float fb = fminf(bt2, bt5) / fmaxf(bt2, bt5);
            float c = lr * tb * fb;
            c = fminf(fmaxf(c, 1e-8f), 1.0f);
            const float ctr = sqrtf(c);
            wsum = ctr;

            const float p0 = bq0.x, p1 = bq0.y, p2 = bq1.x;
            const float p3 = bq1.y, p4 = bq2.x, p5 = bq2.y;
            const float pv = (p0 + p3) * (p1 + p4) * (p2 + p5);
            const float tv = (bt0 + bt3) * (bt1 + bt4) * (bt2 + bt5);
            const float m0 = fminf(p0, bt0), m1 = fminf(p1, bt1), m2 = fminf(p2, bt2);
            const float m3 = fminf(p3, bt3), m4 = fminf(p4, bt4), m5 = fminf(p5, bt5);
            const float inter = (m0 + m3) * (m1 + m4) * (m2 + m5);
            const float uni   = pv + tv - inter;
            const float ious  = (inter + 1.0f) / (uni + 1.0f);
            const float il    = -__logf(fmaxf(ious, 1e-6f));
            wiou = ctr * il;

            const float ec = __expf(-fabsf(ct));
            bce = fmaxf(ct, 0.f) - ct * ctr + __logf(1.0f + ec);
        }
    }

    // block reduction of 5 accumulators -> one store per block per acc
    float vals[5] = { focal, npos, wiou, wsum, bce };
    __shared__ float red[TPB / 32][5];
    const int lane = threadIdx.x & 31;
    const int wid  = threadIdx.x >> 5;
#pragma unroll
    for (int k = 0; k < 5; ++k) {
        const float v = warp_sum(vals[k]);
        if (lane == 0) red[wid][k] = v;
    }
    __syncthreads();
    const int blk = blockIdx.y * gridDim.x + blockIdx.x;
    if (wid == 0 && lane < 5) {
        float v = 0.f;
#pragma unroll
        for (int w = 0; w < TPB / 32; ++w) v += red[w][lane];
        g_part[lane * MAXBLK + blk] = v;
    }

    // ---- last-block-done finalize ----
    __shared__ bool is_last;
    __threadfence();
    if (threadIdx.x == 0) {
        const unsigned int c = atomicAdd(&g_count, 1u);
        is_last = (c == (unsigned int)nblk - 1u);
    }
    __syncthreads();
    if (!is_last) return;

    double acc[5] = {0, 0, 0, 0, 0};
    for (int i = threadIdx.x; i < nblk; i += TPB) {
#pragma unroll
        for (int k = 0; k < 5; ++k) acc[k] += (double)g_part[k * MAXBLK + i];
    }
    __shared__ double dred[TPB / 32][5];
#pragma unroll
    for (int k = 0; k < 5; ++k) {
        double v = acc[k];
#pragma unroll
        for (int o = 16; o; o >>= 1) v += __shfl_down_sync(0xffffffffu, v, o);
        if (lane == 0) dred[wid][k] = v;
    }
    __syncthreads();
    if (threadIdx.x == 0) {
        double t[5];
#pragma unroll
        for (int k = 0; k < 5; ++k) {
            double v = 0.0;
#pragma unroll
            for (int w = 0; w < TPB / 32; ++w) v += dred[w][k];
            t[k] = v;
        }
        out[0] = (float)t[0] / ((float)t[1] + (float)B);
        out[1] = (float)t[2] / fmaxf((float)t[3], 1e-8f);
        out[2] = (float)t[4] / fmaxf((float)t[1], 1.0f);
        g_count = 0;   // reset for next launch / graph replay
    }
}

extern "C" void kernel_launch(void* const* d_in, const int* in_sizes, int n_in,
                              void* d_out, int out_size)
{
    const float* loc  = (const float*)d_in[0];  // [N,3]
    const float* cls  = (const float*)d_in[1];  // [B,N,C]
    const float* boxp = (const float*)d_in[2];  // [B,N,6]
    const float* ctp  = (const float*)d_in[3];  // [B,N]
    const float* bbox = (const float*)d_in[4];  // [B,G,6]
    const int*   glab = (const int*)  d_in[5];  // [B,G]
    // d_in[6] = gt_centers (unused by reference math)
    const float* spt  = (const float*)d_in[7];  // [N]
    const float* soi  = (const float*)d_in[8];  // [N,2]

    const int N = in_sizes[0] / 3;
    const int B = in_sizes[3] / N;
    const int C = in_sizes[1] / (B * N);
    const int G = in_sizes[5] / B;

    float* out = (float*)d_out;

    dim3 grid((N + TPB - 1) / TPB, B);
    const int nblk = grid.x * grid.y;
    fcos_fused_kernel<<<grid, TPB>>>(loc, cls, boxp, ctp, bbox, glab, spt, soi,
                                     out, N, G, C, B, nblk);
}